// round 17
// baseline (speedup 1.0000x reference)
#include <cuda_runtime.h>
#include <cuda_bf16.h>
#include <stdint.h>
#include <math.h>

#define Hh 128
#define NPRc 3000
#define EPRc 6000
#define NTOT 48000
#define NCc 512

__device__ float g_C[(size_t)NTOT*NCc];
__device__ float g_c[(size_t)NTOT*Hh];
__device__ float g_Wt[128*512];
__device__ uint32_t g_Ub2[163840];   // [chunk16][split2][kp8][640] packed bf16x2 of U rows

union F2U { float2 f; unsigned long long u; };
__device__ __forceinline__ float2 ffma2(float2 a, float2 b, float2 c) {
    F2U A,B,C2,D; A.f=a;B.f=b;C2.f=c;
    asm("fma.rn.f32x2 %0, %1, %2, %3;" : "=l"(D.u) : "l"(A.u), "l"(B.u), "l"(C2.u));
    return D.f;
}
__device__ __forceinline__ float2 spl(float b){ return make_float2(b,b); }
__device__ __forceinline__ float sigf(float x){ return 1.0f/(1.0f+expf(-x)); }
__device__ __forceinline__ uint32_t smem_u32(const void* p){
    uint32_t a; asm("{ .reg .u64 t; cvta.to.shared.u64 t, %1; cvt.u32.u64 %0, t; }" : "=r"(a) : "l"(p)); return a;
}
// pack two floats as bf16x2: v0 -> lower 16, v1 -> upper 16
__device__ __forceinline__ uint32_t bf2pk(float v0, float v1){
    uint32_t r; asm("cvt.rn.bf16x2.f32 %0, %1, %2;" : "=r"(r) : "f"(v1), "f"(v0)); return r;
}
__device__ __forceinline__ float bfr(float v){ return __bfloat162float(__float2bfloat16(v)); }

#define MMA(d, A, b0, b1) asm volatile( \
    "mma.sync.aligned.m16n8k16.row.col.f32.bf16.bf16.f32 " \
    "{%0,%1,%2,%3},{%4,%5,%6,%7},{%8,%9},{%0,%1,%2,%3};" \
    : "+f"((d)[0]),"+f"((d)[1]),"+f"((d)[2]),"+f"((d)[3]) \
    : "r"((A)[0]),"r"((A)[1]),"r"((A)[2]),"r"((A)[3]), "r"(b0),"r"(b1))

__device__ __forceinline__ void cpa16(uint32_t dst, const void* src){
    asm volatile("cp.async.cg.shared.global [%0], [%1], 16;" :: "r"(dst), "l"(src));
}
#define CPCOMMIT() asm volatile("cp.async.commit_group;" ::: "memory")
#define CPWAIT0()  asm volatile("cp.async.wait_group 0;" ::: "memory")

// -------------------- k_trans: W^T for k_pre --------------------
__global__ __launch_bounds__(256) void k_trans(const float* __restrict__ W_iou,
                                               const float* __restrict__ W_f) {
    int idx = blockIdx.x*256 + threadIdx.x;
    int k = idx>>9, row = idx&511;
    g_Wt[idx] = (row<384) ? W_iou[row*128+k] : W_f[(row-384)*128+k];
}

// -------------------- k_prepB: split/pack U into mma-chunk layout --------------------
// Output col mapping: [0,384) U_iou rows; [384,512) U_f rows 0-127 (s3);
// [512,640) U_f rows 0-127 AGAIN (s4; same B, different A stream).
__global__ __launch_bounds__(256) void k_prepB(const float* __restrict__ U_iou,
                                               const float* __restrict__ U_f) {
    int idx = blockIdx.x*256 + threadIdx.x;      // 640 blocks -> 163840
    int c = idx/10240, rem = idx%10240;
    int sp = rem/5120, rem2 = rem%5120;
    int kp = rem2/640, col = rem2%640;
    int k = c*16 + kp*2;
    const float* src = (col<384) ? (U_iou + col*256 + k)
                                 : (U_f + ((col-384)&127)*256 + k);
    float v0 = src[0], v1 = src[1];
    if (sp) { v0 = v0 - bfr(v0); v1 = v1 - bfr(v1); }
    g_Ub2[idx] = bf2pk(v0, v1);
}

// -------------------- k_pre (proven) --------------------
#define PRE_SMEMB (17024*4)
__global__ __launch_bounds__(256,2) void k_pre(const float* __restrict__ x) {
    extern __shared__ float sm[];
    float* A = sm; float* Bs = sm+4608; float* xs = sm+12800;
    int t = threadIdx.x, r0 = blockIdx.x*32;
#pragma unroll
    for (int j=0;j<4;j++){ int f=t+256*j,row=f>>5,q=f&31;
        *(float4*)&xs[row*132+4*q] = *((const float4*)(x+(size_t)(r0+row)*128)+q); }
    __syncthreads();
#pragma unroll
    for (int j=0;j<4;j++){ int f=t+256*j,row=f&31,q=f>>5;
        float4 v = *(const float4*)&xs[row*132+4*q];
        A[(4*q+0)*36+row]=v.x; A[(4*q+1)*36+row]=v.y; A[(4*q+2)*36+row]=v.z; A[(4*q+3)*36+row]=v.w; }
#pragma unroll
    for (int j=0;j<4;j++){ int f=t+256*j,ks=f>>7,c4=(f&127)*4;
        *(float4*)&Bs[ks*512+c4] = *(const float4*)&g_Wt[ks*512+c4]; }
    __syncthreads();
    int ct = t&127, rb = (t>>7)*16;
    float2 acc[4][8];
#pragma unroll
    for (int cc=0;cc<4;cc++)
#pragma unroll
        for (int r=0;r<8;r++) acc[cc][r]=make_float2(0.f,0.f);
#pragma unroll 1
    for (int c=0;c<16;c++){
        float4 nb[4];
        if (c<15){
#pragma unroll
            for (int j=0;j<4;j++){ int f=t+256*j,ks=f>>7,c4=(f&127)*4;
                nb[j] = *(const float4*)&g_Wt[((c+1)*8+ks)*512+c4]; } }
        const float* Bb = Bs + (c&1)*4096;
#pragma unroll
        for (int kk=0;kk<8;kk++){
            float2 b0=spl(Bb[kk*512+ct]), b1=spl(Bb[kk*512+128+ct]);
            float2 b2=spl(Bb[kk*512+256+ct]), b3=spl(Bb[kk*512+384+ct]);
            const float* ap = A + (c*8+kk)*36 + rb;
#pragma unroll
            for (int g4=0;g4<4;g4++){
                float4 av = *(const float4*)(ap+4*g4);
                float2 p0=make_float2(av.x,av.y), p1=make_float2(av.z,av.w);
                acc[0][2*g4]=ffma2(b0,p0,acc[0][2*g4]); acc[0][2*g4+1]=ffma2(b0,p1,acc[0][2*g4+1]);
                acc[1][2*g4]=ffma2(b1,p0,acc[1][2*g4]); acc[1][2*g4+1]=ffma2(b1,p1,acc[1][2*g4+1]);
                acc[2][2*g4]=ffma2(b2,p0,acc[2][2*g4]); acc[2][2*g4+1]=ffma2(b2,p1,acc[2][2*g4+1]);
                acc[3][2*g4]=ffma2(b3,p0,acc[3][2*g4]); acc[3][2*g4+1]=ffma2(b3,p1,acc[3][2*g4+1]);
            }
        }
        if (c<15){
            float* d = Bs + ((c+1)&1)*4096;
#pragma unroll
            for (int j=0;j<4;j++){ int f=t+256*j,ks=f>>7,c4=(f&127)*4;
                *(float4*)&d[ks*512+c4] = nb[j]; }
            __syncthreads();
        }
    }
#pragma unroll
    for (int cc=0;cc<4;cc++){
        int col = ct + 128*cc;
#pragma unroll
        for (int r=0;r<8;r++){
            int row = r0 + rb + 2*r;
            g_C[(size_t)row*NCc+col] = acc[cc][r].x;
            g_C[(size_t)(row+1)*NCc+col] = acc[cc][r].y;
        }
    }
}

// -------------------- k_round0 --------------------
__global__ __launch_bounds__(256) void k_round0(float* __restrict__ h,
        const int* __restrict__ order0, const float* __restrict__ b_iou) {
    int idx = blockIdx.x*256 + threadIdx.x;
    if (idx >= NPRc*Hh) return;
    int j = idx>>7, m = idx&127;
    int node = order0[j];
    const float* Cp = g_C + (size_t)node*NCc;
    float gi = Cp[m]+b_iou[m], go = Cp[128+m]+b_iou[128+m], gu = Cp[256+m]+b_iou[256+m];
    float ct = sigf(gi)*tanhf(gu);
    g_c[(size_t)node*Hh+m] = ct;
    h[(size_t)node*Hh+m] = sigf(go)*tanhf(ct);
}

// -------------------- k_rmm: round via mma.sync bf16-split --------------------
// grid 148 x 256 (8 warps). 24 parents (overlapping tiles), M padded to 32.
// A smem u32 [plane4][kp128][40]: planes = {gsum-hi, gsum-lo, he2a-hi, he2a-lo};
// B smem u32 double-buffer [buf2][split2][kp8][648] via cp.async chunks of k16.
// Warp w owns cols 80w..80w+79 (10 n8 frags); stream switch at col 512.
// epi f32 [24][648] aliases A after mainloop. Output cols: [0,384) iou,
// [384,512) s3=U_f@gsum, [512,640) s4=U_f@he2_a.
#define RMM_SMEMB ((20480 + 2*10368) * 4)

__global__ __launch_bounds__(256,1) void k_rmm(int ri, float* __restrict__ h,
        const float* __restrict__ b_iou, const float* __restrict__ b_f,
        const int* __restrict__ edges_r, const float* __restrict__ labels) {
    extern __shared__ uint32_t smu[];
    uint32_t* As = smu;                 // 20480 u32
    uint32_t* Bb = smu + 20480;         // 2 x 10368 u32
    float* hs  = (float*)(smu + 20480); // staging alias (6336 f)
    float* epi = (float*)smu;           // alias after mainloop (24*648)
    __shared__ int s_child[48], s_lab[48], s_par[24];

    int t = threadIdx.x, l = t & 31, w = t >> 5;
    int p0 = 2 * ((int)(blockIdx.x * 1488) / 147);

    const int* e_src = edges_r + ri*2*EPRc;
    const int* e_child = e_src + EPRc;
    const float* labp = labels + ri*EPRc;
    if (t < 48) {
        int e = 2*p0 + t;
        s_child[t] = e_child[e];
        s_lab[t] = (labp[e] != 0.f) ? 1 : 0;
    }
    if (t >= 64 && t < 88) s_par[t-64] = e_src[2*(p0 + t-64)];
    // zero A (incl. padding rows)
#pragma unroll
    for (int j=0;j<20;j++) *(uint4*)&As[(t + 256*j)*4] = make_uint4(0,0,0,0);
    __syncthreads();

    // stage 48 child h rows
#pragma unroll
    for (int j=0;j<6;j++){ int f=t+256*j, e=f>>5, q=f&31;
        *(float4*)&hs[e*132+4*q] = *((const float4*)(h+(size_t)s_child[e]*Hh)+q); }
    __syncthreads();

    // build A planes: cell = (parent, kpair)
#pragma unroll 1
    for (int j=0;j<12;j++){
        int cell = t + 256*j;
        int p = cell % 24, kp = cell / 24, kk = 2*kp;
        const float* hA = hs + (2*p)*132;
        const float* hB = hs + (2*p+1)*132;
        float lA = (float)s_lab[2*p], lB = (float)s_lab[2*p+1];
        float g0, g1, a0, a1;
        if (kk < 128) {
            a0 = (1.f-lA)*hA[kk];   g0 = a0 + (1.f-lB)*hB[kk];
            a1 = (1.f-lA)*hA[kk+1]; g1 = a1 + (1.f-lB)*hB[kk+1];
        } else {
            int km = kk-128;
            a0 = lA*hA[km];   g0 = a0 + lB*hB[km];
            a1 = lA*hA[km+1]; g1 = a1 + lB*hB[km+1];
        }
        float gh0=bfr(g0), gh1=bfr(g1), ah0=bfr(a0), ah1=bfr(a1);
        As[(0*128+kp)*40 + p] = bf2pk(gh0, gh1);
        As[(1*128+kp)*40 + p] = bf2pk(g0-gh0, g1-gh1);
        As[(2*128+kp)*40 + p] = bf2pk(ah0, ah1);
        As[(3*128+kp)*40 + p] = bf2pk(a0-ah0, a1-ah1);
    }
    __syncthreads();            // hs dead; Bb usable

    uint32_t bbase = smem_u32(Bb);
    // issue B chunk 0
#pragma unroll
    for (int j=0;j<10;j++){
        int f = t + 256*j;
        int sp = f/1280, rem = f%1280, kp = rem/160, c4 = (rem%160)*4;
        cpa16(bbase + ((sp*8+kp)*648 + c4)*4, g_Ub2 + (sp*8+kp)*640 + c4);
    }
    CPCOMMIT();

    int cb = 80*w;
    bool needG = (cb < 512), needA = (cb + 72 >= 512);
    int lkq = l & 3, lr = l >> 2;
    float acc[2][10][4];
#pragma unroll
    for (int mh=0;mh<2;mh++)
#pragma unroll
        for (int g=0; g<10; g++)
#pragma unroll
            for (int i=0;i<4;i++) acc[mh][g][i] = 0.f;

#pragma unroll 1
    for (int c=0; c<16; c++) {
        CPWAIT0();
        __syncthreads();
        if (c < 15) {
            int nbuf = (c+1)&1;
#pragma unroll
            for (int j=0;j<10;j++){
                int f = t + 256*j;
                int sp = f/1280, rem = f%1280, kp = rem/160, c4 = (rem%160)*4;
                cpa16(bbase + (nbuf*10368 + (sp*8+kp)*648 + c4)*4,
                      g_Ub2 + ((c+1)*2+sp)*8*640 + kp*640 + c4);
            }
            CPCOMMIT();
        }
        uint32_t agh[2][4], agl[2][4], aah[2][4], aal[2][4];
#pragma unroll
        for (int mh=0; mh<2; mh++) {
            int ro = lr + mh*16;
            if (needG) {
                int b0i = (c*8 + lkq)*40 + ro;
                agh[mh][0]=As[b0i];      agh[mh][1]=As[b0i+8];
                agh[mh][2]=As[b0i+160];  agh[mh][3]=As[b0i+168];
                int b1i = b0i + 5120;
                agl[mh][0]=As[b1i];      agl[mh][1]=As[b1i+8];
                agl[mh][2]=As[b1i+160];  agl[mh][3]=As[b1i+168];
            }
            if (needA) {
                int b2i = (2*128 + c*8 + lkq)*40 + ro;
                aah[mh][0]=As[b2i];      aah[mh][1]=As[b2i+8];
                aah[mh][2]=As[b2i+160];  aah[mh][3]=As[b2i+168];
                int b3i = b2i + 5120;
                aal[mh][0]=As[b3i];      aal[mh][1]=As[b3i+8];
                aal[mh][2]=As[b3i+160];  aal[mh][3]=As[b3i+168];
            }
        }
        const uint32_t* Bc = Bb + (c&1)*10368;
#pragma unroll
        for (int g=0; g<10; g++) {
            int n = cb + g*8 + lr;
            uint32_t bh0 = Bc[lkq*648 + n];
            uint32_t bh1 = Bc[(lkq+4)*648 + n];
            uint32_t bl0 = Bc[(8+lkq)*648 + n];
            uint32_t bl1 = Bc[(8+lkq+4)*648 + n];
            if (cb + g*8 >= 512) {
#pragma unroll
                for (int mh=0; mh<2; mh++) {
                    MMA(acc[mh][g], aah[mh], bh0, bh1);
                    MMA(acc[mh][g], aal[mh], bh0, bh1);
                    MMA(acc[mh][g], aah[mh], bl0, bl1);
                }
            } else {
#pragma unroll
                for (int mh=0; mh<2; mh++) {
                    MMA(acc[mh][g], agh[mh], bh0, bh1);
                    MMA(acc[mh][g], agl[mh], bh0, bh1);
                    MMA(acc[mh][g], agh[mh], bl0, bl1);
                }
            }
        }
    }
    __syncthreads();            // all A reads done before epi overwrite

    // store D -> epi [24][648]
#pragma unroll
    for (int mh=0; mh<2; mh++) {
        int r0 = lr + mh*16, r1 = r0 + 8;
#pragma unroll
        for (int g=0; g<10; g++) {
            int col = cb + g*8 + lkq*2;
            if (r0 < 24) { epi[r0*648+col] = acc[mh][g][0]; epi[r0*648+col+1] = acc[mh][g][1]; }
            if (r1 < 24) { epi[r1*648+col] = acc[mh][g][2]; epi[r1*648+col+1] = acc[mh][g][3]; }
        }
    }
    __syncthreads();

    // fused epilogue (24*128 items)
#pragma unroll 1
    for (int j=0; j<12; j++) {
        int idx = t + 256*j;
        int pl = idx>>7, m = idx&127;
        int par = s_par[pl];
        int cA = s_child[2*pl], cB = s_child[2*pl+1];
        const float* ep = epi + pl*648;
        const float* Cp = g_C + (size_t)par*NCc;
        float gi = Cp[m]     + ep[m]     + b_iou[m];
        float go = Cp[128+m] + ep[128+m] + b_iou[128+m];
        float gu = Cp[256+m] + ep[256+m] + b_iou[256+m];
        float s3 = ep[384+m], s4 = ep[512+m];
        float fa = sigf(g_C[(size_t)cA*NCc+384+m] + s4 + b_f[m]);
        float fb = sigf(g_C[(size_t)cB*NCc+384+m] + (s3-s4) + b_f[m]);
        float ca = g_c[(size_t)cA*Hh+m]; ca = fminf(fmaxf(ca,-1e14f),1e14f);
        float cb2 = g_c[(size_t)cB*Hh+m]; cb2 = fminf(fmaxf(cb2,-1e14f),1e14f);
        float ct2 = sigf(gi)*tanhf(gu) + fa*ca + fb*cb2;
        g_c[(size_t)par*Hh+m] = ct2;
        h[(size_t)par*Hh+m]   = sigf(go)*tanhf(ct2);
    }
}

// -------------------- launcher --------------------
extern "C" void kernel_launch(void* const* d_in, const int* in_sizes, int n_in,
                              void* d_out, int out_size) {
    const float* x      = (const float*)d_in[0];
    const float* labels = (const float*)d_in[1];
    const float* W_iou  = (const float*)d_in[2];
    const float* W_f    = (const float*)d_in[3];
    const float* b_iou  = (const float*)d_in[4];
    const float* b_f    = (const float*)d_in[5];
    const float* U_iou  = (const float*)d_in[6];
    const float* U_f    = (const float*)d_in[7];
    const int*   edges  = (const int*)d_in[8];
    const int*   order0 = (const int*)d_in[9];
    float* h = (float*)d_out;

    cudaFuncSetAttribute(k_pre, cudaFuncAttributeMaxDynamicSharedMemorySize, PRE_SMEMB);
    cudaFuncSetAttribute(k_rmm, cudaFuncAttributeMaxDynamicSharedMemorySize, RMM_SMEMB);

    k_trans<<<256, 256>>>(W_iou, W_f);
    k_prepB<<<640, 256>>>(U_iou, U_f);
    k_pre<<<1500, 256, PRE_SMEMB>>>(x);
    k_round0<<<(NPRc*Hh + 255)/256, 256>>>(h, order0, b_iou);
    for (int ri = 0; ri < 15; ri++)
        k_rmm<<<148, 256, RMM_SMEMB>>>(ri, h, b_iou, b_f, edges, labels);
}